// round 2
// baseline (speedup 1.0000x reference)
#include <cuda_runtime.h>
#include <math.h>

// Fixed problem shape (from setup_inputs)
#define Bb 2
#define L  2048
#define H  64
#define P  64
#define NS 128
#define CS 256
#define NC 8

// ---------------- scratch (static device globals; no runtime alloc) -------
__device__ float g_dt   [Bb*H*NC*CS];            // softplus(dt+bias)
__device__ float g_dacs [Bb*H*NC*CS];            // cumsum(dA) within chunk
__device__ float g_dAl  [Bb*H*NC];               // last cumsum per chunk
__device__ float g_states[(size_t)Bb*NC*H*P*NS]; // chunk end-state contribs
__device__ float g_prev  [(size_t)Bb*NC*H*P*NS]; // propagated prev states
__device__ float g_CB   [(size_t)Bb*NC*CS*CS];   // C @ B^T per (b,c)

// ---------------- K1: dt softplus + per-chunk cumsum ----------------------
__global__ void k_dt(const float* __restrict__ dt, const float* __restrict__ A,
                     const float* __restrict__ dtb) {
    int idx = blockIdx.x;               // b*H*NC
    int c = idx % NC;
    int h = (idx / NC) % H;
    int b = idx / (NC * H);
    int s = threadIdx.x;
    int lg = c * CS + s;

    float v = dt[((size_t)b * L + lg) * H + h] + dtb[h];
    float sp = (v > 20.f) ? v : log1pf(expf(v));
    float dA = sp * A[h];

    __shared__ float sm[CS];
    sm[s] = dA;
    __syncthreads();
#pragma unroll
    for (int off = 1; off < CS; off <<= 1) {
        float pv = (s >= off) ? sm[s - off] : 0.f;
        __syncthreads();
        sm[s] += pv;
        __syncthreads();
    }
    int base = ((b * H + h) * NC + c) * CS;
    g_dt[base + s] = sp;
    g_dacs[base + s] = sm[s];
    if (s == CS - 1) g_dAl[(b * H + h) * NC + c] = sm[s];
}

// ---------------- K2: chunk_state  states[p,n] = sum_s w[s] x[s,p] B[s,n] --
__global__ void __launch_bounds__(256) k_state(const float* __restrict__ x,
                                               const float* __restrict__ Bm) {
    int h = blockIdx.x % H;
    int c = (blockIdx.x / H) % NC;
    int b = blockIdx.x / (H * NC);

    __shared__ float Xs[32][P + 1];   // weighted x tile [k][p]
    __shared__ float Bs[32][NS + 1];  // B tile [k][n]
    __shared__ float ws[32];

    int t = threadIdx.x, ty = t >> 4, tx = t & 15;
    float acc[4][8];
#pragma unroll
    for (int i = 0; i < 4; i++)
#pragma unroll
        for (int j = 0; j < 8; j++) acc[i][j] = 0.f;

    int dbase = ((b * H + h) * NC + c) * CS;
    float dlast = g_dAl[(b * H + h) * NC + c];

    for (int kt = 0; kt < CS; kt += 32) {
        __syncthreads();
        if (t < 32)
            ws[t] = expf(dlast - g_dacs[dbase + kt + t]) * g_dt[dbase + kt + t];
        __syncthreads();
        // load x tile (2048 elems)
#pragma unroll
        for (int i = 0; i < 8; i++) {
            int e = t + 256 * i;
            int k = e >> 6, p = e & 63;
            Xs[k][p] = x[(((size_t)b * L + c * CS + kt + k) * H + h) * P + p] * ws[k];
        }
        // load B tile (4096 elems)
#pragma unroll
        for (int i = 0; i < 16; i++) {
            int e = t + 256 * i;
            int k = e >> 7, n = e & 127;
            Bs[k][n] = Bm[((size_t)b * L + c * CS + kt + k) * NS + n];
        }
        __syncthreads();
#pragma unroll
        for (int k = 0; k < 32; k++) {
            float a[4], bv[8];
#pragma unroll
            for (int i = 0; i < 4; i++) a[i] = Xs[k][ty * 4 + i];
#pragma unroll
            for (int j = 0; j < 8; j++) bv[j] = Bs[k][tx + 16 * j];
#pragma unroll
            for (int i = 0; i < 4; i++)
#pragma unroll
                for (int j = 0; j < 8; j++) acc[i][j] = fmaf(a[i], bv[j], acc[i][j]);
        }
    }
    size_t sbase = (((size_t)(b * NC + c) * H + h) * P) * NS;
#pragma unroll
    for (int i = 0; i < 4; i++)
#pragma unroll
        for (int j = 0; j < 8; j++)
            g_states[sbase + (size_t)(ty * 4 + i) * NS + tx + 16 * j] = acc[i][j];
}

// ---------------- K3: state passing across chunks --------------------------
__global__ void k_pass(float* __restrict__ finals) {
    int e = blockIdx.x % 32;
    int h = (blockIdx.x / 32) % H;
    int b = blockIdx.x / (32 * H);
    int pn = e * 256 + threadIdx.x;    // 0..P*NS-1

    size_t cstride = (size_t)H * P * NS;
    size_t base = ((size_t)b * NC * H + h) * P * NS + pn;
    float run = 0.f;
#pragma unroll
    for (int c = 0; c < NC; c++) {
        size_t idx = base + (size_t)c * cstride;
        g_prev[idx] = run;
        run = run * expf(g_dAl[(b * H + h) * NC + c]) + g_states[idx];
    }
    if (finals) finals[((size_t)(b * H + h)) * P * NS + pn] = run;
}

// ---------------- K4: CB[l,s] = sum_n C[l,n] B[s,n] (per b,c; tril tiles) --
__global__ void __launch_bounds__(256) k_cb(const float* __restrict__ Cm,
                                            const float* __restrict__ Bm) {
    int bc = blockIdx.z;
    int b = bc / NC, c = bc % NC;
    if (blockIdx.x > blockIdx.y) return;  // upper-triangular tiles unused
    int l0 = blockIdx.y * 64, s0 = blockIdx.x * 64;

    __shared__ float Cs[64][33], Bs2[64][33];
    int t = threadIdx.x, ty = t >> 4, tx = t & 15;
    float acc[4][4];
#pragma unroll
    for (int i = 0; i < 4; i++)
#pragma unroll
        for (int j = 0; j < 4; j++) acc[i][j] = 0.f;

    for (int nt = 0; nt < NS; nt += 32) {
        __syncthreads();
#pragma unroll
        for (int i = 0; i < 8; i++) {
            int e = t + 256 * i;
            int r = e >> 5, k = e & 31;
            Cs[r][k]  = Cm[((size_t)b * L + c * CS + l0 + r) * NS + nt + k];
            Bs2[r][k] = Bm[((size_t)b * L + c * CS + s0 + r) * NS + nt + k];
        }
        __syncthreads();
#pragma unroll
        for (int k = 0; k < 32; k++) {
            float a[4], bv[4];
#pragma unroll
            for (int i = 0; i < 4; i++) a[i] = Cs[ty + 16 * i][k];
#pragma unroll
            for (int j = 0; j < 4; j++) bv[j] = Bs2[tx + 16 * j][k];
#pragma unroll
            for (int i = 0; i < 4; i++)
#pragma unroll
                for (int j = 0; j < 4; j++) acc[i][j] = fmaf(a[i], bv[j], acc[i][j]);
        }
    }
    size_t cb = ((size_t)(b * NC + c)) * CS * CS;
#pragma unroll
    for (int i = 0; i < 4; i++)
#pragma unroll
        for (int j = 0; j < 4; j++)
            g_CB[cb + (size_t)(l0 + ty + 16 * i) * CS + s0 + tx + 16 * j] = acc[i][j];
}

// ---------------- K5: chunk_scan (inter + masked intra + epilogue) --------
__global__ void __launch_bounds__(256) k_scan(const float* __restrict__ x,
                                              const float* __restrict__ Cm,
                                              const float* __restrict__ z,
                                              const float* __restrict__ D,
                                              float* __restrict__ out) {
    int tmp = blockIdx.x;
    int lt = tmp & 1; tmp >>= 1;
    int h = tmp % H;  tmp /= H;
    int c = tmp % NC;
    int b = tmp / NC;
    int l0 = lt * 128;

    __shared__ float As[128][33];
    __shared__ float Bs[32][P + 1];
    __shared__ float dl[128];
    __shared__ float sd[32], sdt[32];

    int t = threadIdx.x, ty = t >> 4, tx = t & 15;
    int dbase = ((b * H + h) * NC + c) * CS;
    if (t < 128) dl[t] = g_dacs[dbase + l0 + t];

    float acc[8][4];
#pragma unroll
    for (int i = 0; i < 8; i++)
#pragma unroll
        for (int j = 0; j < 4; j++) acc[i][j] = 0.f;

    // Phase A: inter-chunk term  acc = C[l,:] . prev[p,:]   (K = NS)
    size_t pbase = (((size_t)(b * NC + c) * H + h) * P) * NS;
    for (int nt = 0; nt < NS; nt += 32) {
        __syncthreads();
#pragma unroll
        for (int i = 0; i < 16; i++) {
            int e = t + 256 * i;
            int r = e >> 5, k = e & 31;
            As[r][k] = Cm[((size_t)b * L + c * CS + l0 + r) * NS + nt + k];
        }
#pragma unroll
        for (int i = 0; i < 8; i++) {
            int e = t + 256 * i;
            int p = e >> 5, k = e & 31;
            Bs[k][p] = g_prev[pbase + (size_t)p * NS + nt + k];
        }
        __syncthreads();
#pragma unroll
        for (int k = 0; k < 32; k++) {
            float a[8], bv[4];
#pragma unroll
            for (int i = 0; i < 8; i++) a[i] = As[ty * 8 + i][k];
#pragma unroll
            for (int j = 0; j < 4; j++) bv[j] = Bs[k][tx + 16 * j];
#pragma unroll
            for (int i = 0; i < 8; i++)
#pragma unroll
                for (int j = 0; j < 4; j++) acc[i][j] = fmaf(a[i], bv[j], acc[i][j]);
        }
    }
    // scale inter term by exp(dA_cumsum[l])
#pragma unroll
    for (int i = 0; i < 8; i++) {
        float el = expf(dl[ty * 8 + i]);
#pragma unroll
        for (int j = 0; j < 4; j++) acc[i][j] *= el;
    }

    // Phase B: intra-chunk masked scores  A'[l,s] = CB*exp(dacs[l]-dacs[s])*dt[s]
    size_t cbbase = ((size_t)(b * NC + c)) * CS * CS;
    int nkt = (lt == 0) ? 4 : 8;
    for (int kt = 0; kt < nkt; kt++) {
        int s0 = kt * 32;
        __syncthreads();
        if (t < 32) {
            sd[t]  = g_dacs[dbase + s0 + t];
            sdt[t] = g_dt[dbase + s0 + t];
        }
        __syncthreads();
#pragma unroll
        for (int i = 0; i < 16; i++) {
            int e = t + 256 * i;
            int r = e >> 5, k = e & 31;
            int l = l0 + r, s = s0 + k;
            float v = 0.f;
            if (s <= l)
                v = g_CB[cbbase + (size_t)l * CS + s] * expf(dl[r] - sd[k]) * sdt[k];
            As[r][k] = v;
        }
#pragma unroll
        for (int i = 0; i < 8; i++) {
            int e = t + 256 * i;
            int sr = e >> 6, p = e & 63;
            Bs[sr][p] = x[(((size_t)b * L + c * CS + s0 + sr) * H + h) * P + p];
        }
        __syncthreads();
#pragma unroll
        for (int k = 0; k < 32; k++) {
            float a[8], bv[4];
#pragma unroll
            for (int i = 0; i < 8; i++) a[i] = As[ty * 8 + i][k];
#pragma unroll
            for (int j = 0; j < 4; j++) bv[j] = Bs[k][tx + 16 * j];
#pragma unroll
            for (int i = 0; i < 8; i++)
#pragma unroll
                for (int j = 0; j < 4; j++) acc[i][j] = fmaf(a[i], bv[j], acc[i][j]);
        }
    }

    // Epilogue: + x*D, * silu(z)
    float Dh = D[h];
#pragma unroll
    for (int i = 0; i < 8; i++) {
#pragma unroll
        for (int j = 0; j < 4; j++) {
            int l = l0 + ty * 8 + i, p = tx + 16 * j;
            size_t gi = (((size_t)b * L + c * CS + l) * H + h) * P + p;
            float xv = x[gi], zv = z[gi];
            float o = acc[i][j] + xv * Dh;
            float sil = zv / (1.f + expf(-zv));
            out[gi] = o * sil;
        }
    }
}

// ---------------- launch ----------------------------------------------------
extern "C" void kernel_launch(void* const* d_in, const int* in_sizes, int n_in,
                              void* d_out, int out_size) {
    const float* x   = (const float*)d_in[0];
    const float* dt  = (const float*)d_in[1];
    const float* A   = (const float*)d_in[2];
    const float* Bm  = (const float*)d_in[3];
    const float* Cm  = (const float*)d_in[4];
    const float* D   = (const float*)d_in[5];
    const float* z   = (const float*)d_in[6];
    const float* dtb = (const float*)d_in[7];
    (void)in_sizes; (void)n_in;

    float* out = (float*)d_out;
    const int OUT_ELEMS = Bb * L * H * P;            // 16777216
    const int FIN_ELEMS = Bb * H * P * NS;           // 1048576
    float* finals = (out_size >= OUT_ELEMS + FIN_ELEMS) ? (out + OUT_ELEMS) : nullptr;

    k_dt   <<<Bb * H * NC, CS>>>(dt, A, dtb);
    k_state<<<Bb * NC * H, 256>>>(x, Bm);
    k_pass <<<Bb * H * 32, 256>>>(finals);
    dim3 g4(4, 4, Bb * NC);
    k_cb   <<<g4, 256>>>(Cm, Bm);
    k_scan <<<Bb * NC * H * 2, 256>>>(x, Cm, z, D, out);
}

// round 3
// speedup vs baseline: 1.3041x; 1.3041x over previous
#include <cuda_runtime.h>
#include <math.h>

// Fixed problem shape (from setup_inputs)
#define Bb 2
#define L  2048
#define H  64
#define P  64
#define NS 128
#define CS 256
#define NC 8

// ---------------- scratch (static device globals; no runtime alloc) -------
__device__ float g_dt   [Bb*H*NC*CS];            // softplus(dt+bias)
__device__ float g_dacs [Bb*H*NC*CS];            // cumsum(dA) within chunk
__device__ float g_dAl  [Bb*H*NC];               // last cumsum per chunk
__device__ float g_states[(size_t)Bb*NC*H*P*NS]; // chunk end-state contribs
__device__ float g_prev  [(size_t)Bb*NC*H*P*NS]; // propagated prev states
__device__ float g_CB   [(size_t)Bb*NC*CS*CS];   // C @ B^T per (b,c)

// packed dual-FMA: {c.x,c.y} += {a.x,a.y}*{b.x,b.y}  (one FFMA2 instruction)
__device__ __forceinline__ float2 fma2(float2 a, float2 b, float2 c) {
    unsigned long long ua = *reinterpret_cast<unsigned long long*>(&a);
    unsigned long long ub = *reinterpret_cast<unsigned long long*>(&b);
    unsigned long long uc = *reinterpret_cast<unsigned long long*>(&c);
    asm("fma.rn.f32x2 %0, %1, %2, %0;" : "+l"(uc) : "l"(ua), "l"(ub));
    return *reinterpret_cast<float2*>(&uc);
}

// ---------------- K1: dt softplus + per-chunk cumsum ----------------------
__global__ void k_dt(const float* __restrict__ dt, const float* __restrict__ A,
                     const float* __restrict__ dtb) {
    int idx = blockIdx.x;               // b*H*NC
    int c = idx % NC;
    int h = (idx / NC) % H;
    int b = idx / (NC * H);
    int s = threadIdx.x;
    int lg = c * CS + s;

    float v = dt[((size_t)b * L + lg) * H + h] + dtb[h];
    float sp = (v > 20.f) ? v : log1pf(__expf(v));
    float dA = sp * A[h];

    __shared__ float sm[CS];
    sm[s] = dA;
    __syncthreads();
#pragma unroll
    for (int off = 1; off < CS; off <<= 1) {
        float pv = (s >= off) ? sm[s - off] : 0.f;
        __syncthreads();
        sm[s] += pv;
        __syncthreads();
    }
    int base = ((b * H + h) * NC + c) * CS;
    g_dt[base + s] = sp;
    g_dacs[base + s] = sm[s];
    if (s == CS - 1) g_dAl[(b * H + h) * NC + c] = sm[s];
}

// ---------------- K2: chunk_state  states[p,n] = sum_s w[s] x[s,p] B[s,n] --
// smem layouts are [row][k] so the reduction index k is contiguous (float2).
__global__ void __launch_bounds__(256, 2) k_state(const float* __restrict__ x,
                                                  const float* __restrict__ Bm) {
    int h = blockIdx.x % H;
    int c = (blockIdx.x / H) % NC;
    int b = blockIdx.x / (H * NC);

    __shared__ float Xs[P][34];    // weighted x tile, [p][k]
    __shared__ float Bs[NS][34];   // B tile,         [n][k]
    __shared__ float ws[CS];

    int t = threadIdx.x, ty = t >> 4, tx = t & 15;
    float2 acc2[4][8];
#pragma unroll
    for (int i = 0; i < 4; i++)
#pragma unroll
        for (int j = 0; j < 8; j++) acc2[i][j] = make_float2(0.f, 0.f);

    int dbase = ((b * H + h) * NC + c) * CS;
    float dlast = g_dAl[(b * H + h) * NC + c];
    ws[t] = __expf(dlast - g_dacs[dbase + t]) * g_dt[dbase + t];
    __syncthreads();

    for (int kt = 0; kt < CS; kt += 32) {
        // load x tile (2048 elems), coalesced gmem, transposed smem write
#pragma unroll
        for (int i = 0; i < 8; i++) {
            int e = t + 256 * i;
            int k = e >> 6, p = e & 63;
            Xs[p][k] = x[(((size_t)b * L + c * CS + kt + k) * H + h) * P + p] * ws[kt + k];
        }
        // load B tile (4096 elems)
#pragma unroll
        for (int i = 0; i < 16; i++) {
            int e = t + 256 * i;
            int k = e >> 7, n = e & 127;
            Bs[n][k] = Bm[((size_t)b * L + c * CS + kt + k) * NS + n];
        }
        __syncthreads();
#pragma unroll
        for (int k = 0; k < 32; k += 2) {
            float2 a2[4], b2[8];
#pragma unroll
            for (int i = 0; i < 4; i++) a2[i] = *(const float2*)&Xs[ty * 4 + i][k];
#pragma unroll
            for (int j = 0; j < 8; j++) b2[j] = *(const float2*)&Bs[tx + 16 * j][k];
#pragma unroll
            for (int i = 0; i < 4; i++)
#pragma unroll
                for (int j = 0; j < 8; j++) acc2[i][j] = fma2(a2[i], b2[j], acc2[i][j]);
        }
        __syncthreads();
    }
    size_t sbase = (((size_t)(b * NC + c) * H + h) * P) * NS;
#pragma unroll
    for (int i = 0; i < 4; i++)
#pragma unroll
        for (int j = 0; j < 8; j++)
            g_states[sbase + (size_t)(ty * 4 + i) * NS + tx + 16 * j] =
                acc2[i][j].x + acc2[i][j].y;
}

// ---------------- K3: state passing across chunks --------------------------
__global__ void k_pass(float* __restrict__ finals) {
    int e = blockIdx.x % 32;
    int h = (blockIdx.x / 32) % H;
    int b = blockIdx.x / (32 * H);
    int pn = e * 256 + threadIdx.x;    // 0..P*NS-1

    size_t cstride = (size_t)H * P * NS;
    size_t base = ((size_t)b * NC * H + h) * P * NS + pn;
    float run = 0.f;
#pragma unroll
    for (int c = 0; c < NC; c++) {
        size_t idx = base + (size_t)c * cstride;
        g_prev[idx] = run;
        run = run * __expf(g_dAl[(b * H + h) * NC + c]) + g_states[idx];
    }
    if (finals) finals[((size_t)(b * H + h)) * P * NS + pn] = run;
}

// ---------------- K4: CB[l,s] = sum_n C[l,n] B[s,n] (per b,c; tril tiles) --
__global__ void __launch_bounds__(256, 2) k_cb(const float* __restrict__ Cm,
                                               const float* __restrict__ Bm) {
    int bc = blockIdx.z;
    int b = bc / NC, c = bc % NC;
    if (blockIdx.x > blockIdx.y) return;  // upper-triangular tiles unused
    int l0 = blockIdx.y * 64, s0 = blockIdx.x * 64;

    __shared__ float Cs[64][34], Bs2[64][34];
    int t = threadIdx.x, ty = t >> 4, tx = t & 15;
    float2 acc2[4][4];
#pragma unroll
    for (int i = 0; i < 4; i++)
#pragma unroll
        for (int j = 0; j < 4; j++) acc2[i][j] = make_float2(0.f, 0.f);

    for (int nt = 0; nt < NS; nt += 32) {
#pragma unroll
        for (int i = 0; i < 8; i++) {
            int e = t + 256 * i;
            int r = e >> 5, k = e & 31;
            Cs[r][k]  = Cm[((size_t)b * L + c * CS + l0 + r) * NS + nt + k];
            Bs2[r][k] = Bm[((size_t)b * L + c * CS + s0 + r) * NS + nt + k];
        }
        __syncthreads();
#pragma unroll
        for (int k = 0; k < 32; k += 2) {
            float2 a2[4], b2[4];
#pragma unroll
            for (int i = 0; i < 4; i++) a2[i] = *(const float2*)&Cs[ty + 16 * i][k];
#pragma unroll
            for (int j = 0; j < 4; j++) b2[j] = *(const float2*)&Bs2[tx + 16 * j][k];
#pragma unroll
            for (int i = 0; i < 4; i++)
#pragma unroll
                for (int j = 0; j < 4; j++) acc2[i][j] = fma2(a2[i], b2[j], acc2[i][j]);
        }
        __syncthreads();
    }
    size_t cb = ((size_t)(b * NC + c)) * CS * CS;
#pragma unroll
    for (int i = 0; i < 4; i++)
#pragma unroll
        for (int j = 0; j < 4; j++)
            g_CB[cb + (size_t)(l0 + ty + 16 * i) * CS + s0 + tx + 16 * j] =
                acc2[i][j].x + acc2[i][j].y;
}

// ---------------- K5: chunk_scan (inter + masked intra + epilogue) --------
__global__ void __launch_bounds__(256, 2) k_scan(const float* __restrict__ x,
                                                 const float* __restrict__ Cm,
                                                 const float* __restrict__ z,
                                                 const float* __restrict__ D,
                                                 float* __restrict__ out) {
    int tmp = blockIdx.x;
    int lt = tmp & 1; tmp >>= 1;
    int h = tmp % H;  tmp /= H;
    int c = tmp % NC;
    int b = tmp / NC;
    int l0 = lt * 128;

    __shared__ float As[128][34];   // operand A tile [r][k]
    __shared__ float Bs[64][34];    // operand B tile [col-row][k]
    __shared__ float sdall[CS], sdtall[CS];

    int t = threadIdx.x, ty = t >> 4, tx = t & 15;
    int dbase = ((b * H + h) * NC + c) * CS;
    sdall[t]  = g_dacs[dbase + t];
    sdtall[t] = g_dt[dbase + t];

    float2 acc2[8][4];
#pragma unroll
    for (int i = 0; i < 8; i++)
#pragma unroll
        for (int j = 0; j < 4; j++) acc2[i][j] = make_float2(0.f, 0.f);

    // Phase A: inter-chunk term  acc = C[l,:] . prev[p,:]   (K = NS)
    size_t pbase = (((size_t)(b * NC + c) * H + h) * P) * NS;
    for (int nt = 0; nt < NS; nt += 32) {
        __syncthreads();
#pragma unroll
        for (int i = 0; i < 16; i++) {
            int e = t + 256 * i;
            int r = e >> 5, k = e & 31;
            As[r][k] = Cm[((size_t)b * L + c * CS + l0 + r) * NS + nt + k];
        }
#pragma unroll
        for (int i = 0; i < 8; i++) {
            int e = t + 256 * i;
            int p = e >> 5, k = e & 31;
            Bs[p][k] = g_prev[pbase + (size_t)p * NS + nt + k];
        }
        __syncthreads();
#pragma unroll
        for (int k = 0; k < 32; k += 2) {
            float2 a2[8], b2[4];
#pragma unroll
            for (int i = 0; i < 8; i++) a2[i] = *(const float2*)&As[ty * 8 + i][k];
#pragma unroll
            for (int j = 0; j < 4; j++) b2[j] = *(const float2*)&Bs[tx + 16 * j][k];
#pragma unroll
            for (int i = 0; i < 8; i++)
#pragma unroll
                for (int j = 0; j < 4; j++) acc2[i][j] = fma2(a2[i], b2[j], acc2[i][j]);
        }
    }
    // scale inter term by exp(dA_cumsum[l]) (packed mul, still in acc2)
#pragma unroll
    for (int i = 0; i < 8; i++) {
        float el = __expf(sdall[l0 + ty * 8 + i]);
#pragma unroll
        for (int j = 0; j < 4; j++) { acc2[i][j].x *= el; acc2[i][j].y *= el; }
    }

    // Phase B: intra-chunk masked scores  A'[l,s] = CB*exp(dacs[l]-dacs[s])*dt[s]
    size_t cbbase = ((size_t)(b * NC + c)) * CS * CS;
    int nkt = (lt == 0) ? 4 : 8;
    for (int kt = 0; kt < nkt; kt++) {
        int s0 = kt * 32;
        __syncthreads();
#pragma unroll
        for (int i = 0; i < 16; i++) {
            int e = t + 256 * i;
            int r = e >> 5, k = e & 31;
            int l = l0 + r, s = s0 + k;
            float v = 0.f;
            if (s <= l)
                v = g_CB[cbbase + (size_t)l * CS + s] *
                    __expf(sdall[l0 + r] - sdall[s0 + k]) * sdtall[s0 + k];
            As[r][k] = v;
        }
#pragma unroll
        for (int i = 0; i < 8; i++) {
            int e = t + 256 * i;
            int sr = e >> 6, p = e & 63;
            Bs[p][sr] = x[(((size_t)b * L + c * CS + s0 + sr) * H + h) * P + p];
        }
        __syncthreads();
#pragma unroll
        for (int k = 0; k < 32; k += 2) {
            float2 a2[8], b2[4];
#pragma unroll
            for (int i = 0; i < 8; i++) a2[i] = *(const float2*)&As[ty * 8 + i][k];
#pragma unroll
            for (int j = 0; j < 4; j++) b2[j] = *(const float2*)&Bs[tx + 16 * j][k];
#pragma unroll
            for (int i = 0; i < 8; i++)
#pragma unroll
                for (int j = 0; j < 4; j++) acc2[i][j] = fma2(a2[i], b2[j], acc2[i][j]);
        }
    }

    // Epilogue: fold k-parity, + x*D, * silu(z)
    float Dh = D[h];
#pragma unroll
    for (int i = 0; i < 8; i++) {
#pragma unroll
        for (int j = 0; j < 4; j++) {
            int l = l0 + ty * 8 + i, p = tx + 16 * j;
            size_t gi = (((size_t)b * L + c * CS + l) * H + h) * P + p;
            float xv = x[gi], zv = z[gi];
            float o = acc2[i][j].x + acc2[i][j].y + xv * Dh;
            float sil = zv / (1.f + __expf(-zv));
            out[gi] = o * sil;
        }
    }
}

// ---------------- launch ----------------------------------------------------
extern "C" void kernel_launch(void* const* d_in, const int* in_sizes, int n_in,
                              void* d_out, int out_size) {
    const float* x   = (const float*)d_in[0];
    const float* dt  = (const float*)d_in[1];
    const float* A   = (const float*)d_in[2];
    const float* Bm  = (const float*)d_in[3];
    const float* Cm  = (const float*)d_in[4];
    const float* D   = (const float*)d_in[5];
    const float* z   = (const float*)d_in[6];
    const float* dtb = (const float*)d_in[7];
    (void)in_sizes; (void)n_in;

    float* out = (float*)d_out;
    const int OUT_ELEMS = Bb * L * H * P;            // 16777216
    const int FIN_ELEMS = Bb * H * P * NS;           // 1048576
    float* finals = (out_size >= OUT_ELEMS + FIN_ELEMS) ? (out + OUT_ELEMS) : nullptr;

    k_dt   <<<Bb * H * NC, CS>>>(dt, A, dtb);
    k_state<<<Bb * NC * H, 256>>>(x, Bm);
    k_pass <<<Bb * H * 32, 256>>>(finals);
    dim3 g4(4, 4, Bb * NC);
    k_cb   <<<g4, 256>>>(Cm, Bm);
    k_scan <<<Bb * NC * H * 2, 256>>>(x, Cm, z, D, out);
}

// round 4
// speedup vs baseline: 1.3126x; 1.0065x over previous
#include <cuda_runtime.h>
#include <math.h>

// Fixed problem shape (from setup_inputs)
#define Bb 2
#define L  2048
#define H  64
#define P  64
#define NS 128
#define CS 256
#define NC 8

// ---------------- scratch (static device globals; no runtime alloc) -------
__device__ float g_dt   [Bb*H*NC*CS];            // softplus(dt+bias)
__device__ float g_dacs [Bb*H*NC*CS];            // cumsum(dA) within chunk
__device__ float g_dAl  [Bb*H*NC];               // last cumsum per chunk
__device__ float g_states[(size_t)Bb*NC*H*P*NS]; // chunk end-state contribs
__device__ float g_prev  [(size_t)Bb*NC*H*P*NS]; // propagated prev states
__device__ float g_CB   [(size_t)Bb*NC*CS*CS];   // C @ B^T per (b,c)

// packed dual-FMA: {c.x,c.y} += {a.x,a.y}*{b.x,b.y}  (one FFMA2 instruction)
__device__ __forceinline__ float2 fma2(float2 a, float2 b, float2 c) {
    unsigned long long ua = *reinterpret_cast<unsigned long long*>(&a);
    unsigned long long ub = *reinterpret_cast<unsigned long long*>(&b);
    unsigned long long uc = *reinterpret_cast<unsigned long long*>(&c);
    asm("fma.rn.f32x2 %0, %1, %2, %0;" : "+l"(uc) : "l"(ua), "l"(ub));
    return *reinterpret_cast<float2*>(&uc);
}

// ---------------- K1: dt softplus + per-chunk cumsum ----------------------
__global__ void k_dt(const float* __restrict__ dt, const float* __restrict__ A,
                     const float* __restrict__ dtb) {
    int idx = blockIdx.x;               // b*H*NC
    int c = idx % NC;
    int h = (idx / NC) % H;
    int b = idx / (NC * H);
    int s = threadIdx.x;
    int lg = c * CS + s;

    float v = dt[((size_t)b * L + lg) * H + h] + dtb[h];
    float sp = (v > 20.f) ? v : log1pf(__expf(v));
    float dA = sp * A[h];

    __shared__ float sm[CS];
    sm[s] = dA;
    __syncthreads();
#pragma unroll
    for (int off = 1; off < CS; off <<= 1) {
        float pv = (s >= off) ? sm[s - off] : 0.f;
        __syncthreads();
        sm[s] += pv;
        __syncthreads();
    }
    int base = ((b * H + h) * NC + c) * CS;
    g_dt[base + s] = sp;
    g_dacs[base + s] = sm[s];
    if (s == CS - 1) g_dAl[(b * H + h) * NC + c] = sm[s];
}

// ---------------- K2: chunk_state  states[p,n] = sum_s w[s] x[s,p] B[s,n] --
// smem layouts are [row][k] so the reduction index k is contiguous (float2).
__global__ void __launch_bounds__(256, 2) k_state(const float* __restrict__ x,
                                                  const float* __restrict__ Bm) {
    int h = blockIdx.x % H;
    int c = (blockIdx.x / H) % NC;
    int b = blockIdx.x / (H * NC);

    __shared__ float Xs[P][34];    // weighted x tile, [p][k]
    __shared__ float Bs[NS][34];   // B tile,         [n][k]
    __shared__ float ws[CS];

    int t = threadIdx.x, ty = t >> 4, tx = t & 15;
    float2 acc2[4][8];
#pragma unroll
    for (int i = 0; i < 4; i++)
#pragma unroll
        for (int j = 0; j < 8; j++) acc2[i][j] = make_float2(0.f, 0.f);

    int dbase = ((b * H + h) * NC + c) * CS;
    float dlast = g_dAl[(b * H + h) * NC + c];
    ws[t] = __expf(dlast - g_dacs[dbase + t]) * g_dt[dbase + t];
    __syncthreads();

    for (int kt = 0; kt < CS; kt += 32) {
        // load x tile (2048 elems), coalesced gmem, transposed smem write
#pragma unroll
        for (int i = 0; i < 8; i++) {
            int e = t + 256 * i;
            int k = e >> 6, p = e & 63;
            Xs[p][k] = x[(((size_t)b * L + c * CS + kt + k) * H + h) * P + p] * ws[kt + k];
        }
        // load B tile (4096 elems)
#pragma unroll
        for (int i = 0; i < 16; i++) {
            int e = t + 256 * i;
            int k = e >> 7, n = e & 127;
            Bs[n][k] = Bm[((size_t)b * L + c * CS + kt + k) * NS + n];
        }
        __syncthreads();
#pragma unroll
        for (int k = 0; k < 32; k += 2) {
            float2 a2[4], b2[8];
#pragma unroll
            for (int i = 0; i < 4; i++) a2[i] = *(const float2*)&Xs[ty * 4 + i][k];
#pragma unroll
            for (int j = 0; j < 8; j++) b2[j] = *(const float2*)&Bs[tx + 16 * j][k];
#pragma unroll
            for (int i = 0; i < 4; i++)
#pragma unroll
                for (int j = 0; j < 8; j++) acc2[i][j] = fma2(a2[i], b2[j], acc2[i][j]);
        }
        __syncthreads();
    }
    size_t sbase = (((size_t)(b * NC + c) * H + h) * P) * NS;
#pragma unroll
    for (int i = 0; i < 4; i++)
#pragma unroll
        for (int j = 0; j < 8; j++)
            g_states[sbase + (size_t)(ty * 4 + i) * NS + tx + 16 * j] =
                acc2[i][j].x + acc2[i][j].y;
}

// ---------------- K3: state passing across chunks --------------------------
__global__ void k_pass(float* __restrict__ finals) {
    int e = blockIdx.x % 32;
    int h = (blockIdx.x / 32) % H;
    int b = blockIdx.x / (32 * H);
    int pn = e * 256 + threadIdx.x;    // 0..P*NS-1

    size_t cstride = (size_t)H * P * NS;
    size_t base = ((size_t)b * NC * H + h) * P * NS + pn;
    float run = 0.f;
#pragma unroll
    for (int c = 0; c < NC; c++) {
        size_t idx = base + (size_t)c * cstride;
        g_prev[idx] = run;
        run = run * __expf(g_dAl[(b * H + h) * NC + c]) + g_states[idx];
    }
    if (finals) finals[((size_t)(b * H + h)) * P * NS + pn] = run;
}

// ---------------- K4: CB[l,s] = sum_n C[l,n] B[s,n] (per b,c; tril tiles) --
__global__ void __launch_bounds__(256, 2) k_cb(const float* __restrict__ Cm,
                                               const float* __restrict__ Bm) {
    int bc = blockIdx.z;
    int b = bc / NC, c = bc % NC;
    if (blockIdx.x > blockIdx.y) return;  // upper-triangular tiles unused
    int l0 = blockIdx.y * 64, s0 = blockIdx.x * 64;

    __shared__ float Cs[64][34], Bs2[64][34];
    int t = threadIdx.x, ty = t >> 4, tx = t & 15;
    float2 acc2[4][4];
#pragma unroll
    for (int i = 0; i < 4; i++)
#pragma unroll
        for (int j = 0; j < 4; j++) acc2[i][j] = make_float2(0.f, 0.f);

    for (int nt = 0; nt < NS; nt += 32) {
#pragma unroll
        for (int i = 0; i < 8; i++) {
            int e = t + 256 * i;
            int r = e >> 5, k = e & 31;
            Cs[r][k]  = Cm[((size_t)b * L + c * CS + l0 + r) * NS + nt + k];
            Bs2[r][k] = Bm[((size_t)b * L + c * CS + s0 + r) * NS + nt + k];
        }
        __syncthreads();
#pragma unroll
        for (int k = 0; k < 32; k += 2) {
            float2 a2[4], b2[4];
#pragma unroll
            for (int i = 0; i < 4; i++) a2[i] = *(const float2*)&Cs[ty + 16 * i][k];
#pragma unroll
            for (int j = 0; j < 4; j++) b2[j] = *(const float2*)&Bs2[tx + 16 * j][k];
#pragma unroll
            for (int i = 0; i < 4; i++)
#pragma unroll
                for (int j = 0; j < 4; j++) acc2[i][j] = fma2(a2[i], b2[j], acc2[i][j]);
        }
        __syncthreads();
    }
    size_t cb = ((size_t)(b * NC + c)) * CS * CS;
#pragma unroll
    for (int i = 0; i < 4; i++)
#pragma unroll
        for (int j = 0; j < 4; j++)
            g_CB[cb + (size_t)(l0 + ty + 16 * i) * CS + s0 + tx + 16 * j] =
                acc2[i][j].x + acc2[i][j].y;
}

// ---------------- K5: chunk_scan (inter + masked intra + epilogue) --------
__global__ void __launch_bounds__(256, 2) k_scan(const float* __restrict__ x,
                                                 const float* __restrict__ Cm,
                                                 const float* __restrict__ z,
                                                 const float* __restrict__ D,
                                                 float* __restrict__ out) {
    int tmp = blockIdx.x;
    int lt = tmp & 1; tmp >>= 1;
    int h = tmp % H;  tmp /= H;
    int c = tmp % NC;
    int b = tmp / NC;
    int l0 = lt * 128;

    __shared__ float As[128][34];   // operand A tile [r][k]
    __shared__ float Bs[64][34];    // operand B tile [col-row][k]
    __shared__ float sdall[CS], sdtall[CS];

    int t = threadIdx.x, ty = t >> 4, tx = t & 15;
    int dbase = ((b * H + h) * NC + c) * CS;
    sdall[t]  = g_dacs[dbase + t];
    sdtall[t] = g_dt[dbase + t];

    float2 acc2[8][4];
#pragma unroll
    for (int i = 0; i < 8; i++)
#pragma unroll
        for (int j = 0; j < 4; j++) acc2[i][j] = make_float2(0.f, 0.f);

    // Phase A: inter-chunk term  acc = C[l,:] . prev[p,:]   (K = NS)
    size_t pbase = (((size_t)(b * NC + c) * H + h) * P) * NS;
    for (int nt = 0; nt < NS; nt += 32) {
        __syncthreads();
#pragma unroll
        for (int i = 0; i < 16; i++) {
            int e = t + 256 * i;
            int r = e >> 5, k = e & 31;
            As[r][k] = Cm[((size_t)b * L + c * CS + l0 + r) * NS + nt + k];
        }
#pragma unroll
        for (int i = 0; i < 8; i++) {
            int e = t + 256 * i;
            int p = e >> 5, k = e & 31;
            Bs[p][k] = g_prev[pbase + (size_t)p * NS + nt + k];
        }
        __syncthreads();
#pragma unroll
        for (int k = 0; k < 32; k += 2) {
            float2 a2[8], b2[4];
#pragma unroll
            for (int i = 0; i < 8; i++) a2[i] = *(const float2*)&As[ty * 8 + i][k];
#pragma unroll
            for (int j = 0; j < 4; j++) b2[j] = *(const float2*)&Bs[tx + 16 * j][k];
#pragma unroll
            for (int i = 0; i < 8; i++)
#pragma unroll
                for (int j = 0; j < 4; j++) acc2[i][j] = fma2(a2[i], b2[j], acc2[i][j]);
        }
    }
    // scale inter term by exp(dA_cumsum[l]) (packed mul, still in acc2)
#pragma unroll
    for (int i = 0; i < 8; i++) {
        float el = __expf(sdall[l0 + ty * 8 + i]);
#pragma unroll
        for (int j = 0; j < 4; j++) { acc2[i][j].x *= el; acc2[i][j].y *= el; }
    }

    // Phase B: intra-chunk masked scores  A'[l,s] = CB*exp(dacs[l]-dacs[s])*dt[s]
    size_t cbbase = ((size_t)(b * NC + c)) * CS * CS;
    int nkt = (lt == 0) ? 4 : 8;
    for (int kt = 0; kt < nkt; kt++) {
        int s0 = kt * 32;
        __syncthreads();
#pragma unroll
        for (int i = 0; i < 16; i++) {
            int e = t + 256 * i;
            int r = e >> 5, k = e & 31;
            int l = l0 + r, s = s0 + k;
            float v = 0.f;
            if (s <= l)
                v = g_CB[cbbase + (size_t)l * CS + s] *
                    __expf(sdall[l0 + r] - sdall[s0 + k]) * sdtall[s0 + k];
            As[r][k] = v;
        }
#pragma unroll
        for (int i = 0; i < 8; i++) {
            int e = t + 256 * i;
            int sr = e >> 6, p = e & 63;
            Bs[p][sr] = x[(((size_t)b * L + c * CS + s0 + sr) * H + h) * P + p];
        }
        __syncthreads();
#pragma unroll
        for (int k = 0; k < 32; k += 2) {
            float2 a2[8], b2[4];
#pragma unroll
            for (int i = 0; i < 8; i++) a2[i] = *(const float2*)&As[ty * 8 + i][k];
#pragma unroll
            for (int j = 0; j < 4; j++) b2[j] = *(const float2*)&Bs[tx + 16 * j][k];
#pragma unroll
            for (int i = 0; i < 8; i++)
#pragma unroll
                for (int j = 0; j < 4; j++) acc2[i][j] = fma2(a2[i], b2[j], acc2[i][j]);
        }
    }

    // Epilogue: fold k-parity, + x*D, * silu(z)
    float Dh = D[h];
#pragma unroll
    for (int i = 0; i < 8; i++) {
#pragma unroll
        for (int j = 0; j < 4; j++) {
            int l = l0 + ty * 8 + i, p = tx + 16 * j;
            size_t gi = (((size_t)b * L + c * CS + l) * H + h) * P + p;
            float xv = x[gi], zv = z[gi];
            float o = acc2[i][j].x + acc2[i][j].y + xv * Dh;
            float sil = zv / (1.f + __expf(-zv));
            out[gi] = o * sil;
        }
    }
}

// ---------------- launch ----------------------------------------------------
extern "C" void kernel_launch(void* const* d_in, const int* in_sizes, int n_in,
                              void* d_out, int out_size) {
    const float* x   = (const float*)d_in[0];
    const float* dt  = (const float*)d_in[1];
    const float* A   = (const float*)d_in[2];
    const float* Bm  = (const float*)d_in[3];
    const float* Cm  = (const float*)d_in[4];
    const float* D   = (const float*)d_in[5];
    const float* z   = (const float*)d_in[6];
    const float* dtb = (const float*)d_in[7];
    (void)in_sizes; (void)n_in;

    float* out = (float*)d_out;
    const int OUT_ELEMS = Bb * L * H * P;            // 16777216
    const int FIN_ELEMS = Bb * H * P * NS;           // 1048576
    float* finals = (out_size >= OUT_ELEMS + FIN_ELEMS) ? (out + OUT_ELEMS) : nullptr;

    k_dt   <<<Bb * H * NC, CS>>>(dt, A, dtb);
    k_state<<<Bb * NC * H, 256>>>(x, Bm);
    k_pass <<<Bb * H * 32, 256>>>(finals);
    dim3 g4(4, 4, Bb * NC);
    k_cb   <<<g4, 256>>>(Cm, Bm);
    k_scan <<<Bb * NC * H * 2, 256>>>(x, Cm, z, D, out);
}